// round 16
// baseline (speedup 1.0000x reference)
#include <cuda_runtime.h>
#include <cuda_bf16.h>
#include <stdint.h>
#include <math.h>

#define LDIM 1024
#define CDIM 256
#define NB   16

// ---------------- scratch (device globals) ----------------
__device__ uint16_t g_w_hi[768 * 256], g_w_lo[768 * 256];   // wt, wp, W2 stacked
__device__ float    g_w2f[256 * 256];                        // W2 = wr @ wg (fp32)
__device__ uint16_t g_x_hi[16ull * 256 * 1024], g_x_lo[16ull * 256 * 1024];
__device__ uint16_t g_tpg_hi[3ull * 16 * 256 * 1024], g_tpg_lo[3ull * 16 * 256 * 1024];
__device__ float g_partm[16 * 64], g_parts[16 * 64], g_M[16], g_invZ[16];

// ---------------- helpers ----------------
__device__ __forceinline__ uint32_t smem_u32(const void* p) {
    uint32_t a;
    asm("{ .reg .u64 t; cvta.to.shared.u64 t, %1; cvt.u32.u64 %0, t; }" : "=r"(a) : "l"(p));
    return a;
}
__device__ __forceinline__ void hmma(float* c, const uint32_t* a, const uint32_t* b) {
    asm volatile(
        "mma.sync.aligned.m16n8k16.row.col.f32.bf16.bf16.f32 "
        "{%0,%1,%2,%3}, {%4,%5,%6,%7}, {%8,%9}, {%0,%1,%2,%3};"
        : "+f"(c[0]), "+f"(c[1]), "+f"(c[2]), "+f"(c[3])
        : "r"(a[0]), "r"(a[1]), "r"(a[2]), "r"(a[3]), "r"(b[0]), "r"(b[1]));
}
__device__ __forceinline__ void ldsm4(uint32_t* r, uint32_t addr) {
    asm volatile("ldmatrix.sync.aligned.m8n8.x4.shared.b16 {%0,%1,%2,%3}, [%4];"
                 : "=r"(r[0]), "=r"(r[1]), "=r"(r[2]), "=r"(r[3]) : "r"(addr));
}
__device__ __forceinline__ void ldsm4t(uint32_t* r, uint32_t addr) {
    asm volatile("ldmatrix.sync.aligned.m8n8.x4.trans.shared.b16 {%0,%1,%2,%3}, [%4];"
                 : "=r"(r[0]), "=r"(r[1]), "=r"(r[2]), "=r"(r[3]) : "r"(addr));
}
__device__ __forceinline__ void cp16(uint32_t daddr, const void* src) {
    asm volatile("cp.async.cg.shared.global [%0], [%1], 16;" ::"r"(daddr), "l"(src) : "memory");
}
#define CP_COMMIT() asm volatile("cp.async.commit_group;" ::: "memory")
#define CP_WAIT(n)  asm volatile("cp.async.wait_group %0;" ::"n"(n) : "memory")

__device__ __forceinline__ uint32_t pk2(float a, float b) {
    __nv_bfloat162 t = __floats2bfloat162_rn(a, b);
    return reinterpret_cast<uint32_t&>(t);
}
__device__ __forceinline__ void wrpair(uint16_t* hi, uint16_t* lo, float a, float b) {
    float ha = __bfloat162float(__float2bfloat16(a));
    float hb = __bfloat162float(__float2bfloat16(b));
    *(uint32_t*)hi = pk2(a, b);
    *(uint32_t*)lo = pk2(a - ha, b - hb);
}

// ---------------- W2 = wr @ wg (fp32, tiny) ----------------
__global__ __launch_bounds__(256) void k_w2(const float* __restrict__ wr,
                                            const float* __restrict__ wg) {
    __shared__ float wrow[256];
    const int c = blockIdx.x, i = threadIdx.x;
    wrow[i] = wr[c * 256 + i];
    __syncthreads();
    float s = 0.f;
#pragma unroll 8
    for (int a = 0; a < 256; a++) s = fmaf(wrow[a], wg[a * 256 + i], s);
    g_w2f[c * 256 + i] = s;
}

// ---------------- conversion passes ----------------
__global__ __launch_bounds__(256) void k_cvt_w(const float* __restrict__ wt,
                                               const float* __restrict__ wp) {
    int idx = blockIdx.x * 256 + threadIdx.x;
    int e = idx * 4, row = e >> 8, col = e & 255;
    const float* s = (row < 256) ? wt + (size_t)row * 256
                   : (row < 512) ? wp + (size_t)(row - 256) * 256
                                 : g_w2f + (size_t)(row - 512) * 256;
    float4 v = *(const float4*)(s + col);
    size_t o = (size_t)row * 256 + col;
    wrpair(g_w_hi + o, g_w_lo + o, v.x, v.y);
    wrpair(g_w_hi + o + 2, g_w_lo + o + 2, v.z, v.w);
}
__global__ __launch_bounds__(256) void k_cvt_x(const float* __restrict__ x) {
    size_t idx = (size_t)blockIdx.x * 256 + threadIdx.x;
    float4 v = ((const float4*)x)[idx];
    size_t o = idx * 4;
    wrpair(g_x_hi + o, g_x_lo + o, v.x, v.y);
    wrpair(g_x_hi + o + 2, g_x_lo + o + 2, v.z, v.w);
}

// =====================================================================
// Pipelined mma.sync GEMM: 128x128 block, BK=32, 3-stage ring, one sync
// per stage, 2 CTAs/SM, cp.async issued AFTER the barrier (wrap-safe).
// 8 warps (64x32 warp tile), bf16 hi/lo 3-term split.
// MODE: 0=t,p,G2   1=c (A = t via ldmatrix.trans, fused softmax partial)
//       2=y = x + iZ * (G2 @ exp(c - M))
// =====================================================================
template <int MODE>
__global__ __launch_bounds__(256, 2) void gemm_mma(const float* __restrict__ x,
                                                   float* __restrict__ cbuf,
                                                   float* __restrict__ ybuf) {
    constexpr int S     = (MODE == 2) ? 32 : 8;                // K/32 stages
    constexpr int APL   = (MODE == 1) ? 32 * 136 : 128 * 40;   // A plane elems
    constexpr int BPL   = 32 * 136;
    constexpr int STAGE = 2 * APL + 2 * BPL;
    extern __shared__ __align__(16) uint16_t smbuf[];

    const int tid = threadIdx.x, lane = tid & 31, wid = tid >> 5;
    const int n = blockIdx.z, j0 = blockIdx.x * 128, m0 = blockIdx.y * 128;
    const int wm = (wid & 1) * 64, wn = (wid >> 1) * 32;

    const uint16_t *Aph, *Apl, *Bph = nullptr, *Bpl = nullptr;
    const float* Bf = nullptr;
    float eM = 0.f, iZ = 1.f;
    size_t AKW = 256;
    if (MODE == 0) {
        Aph = g_w_hi + (size_t)m0 * 256;  Apl = g_w_lo + (size_t)m0 * 256;
        Bph = g_x_hi + (size_t)n * CDIM * LDIM;  Bpl = g_x_lo + (size_t)n * CDIM * LDIM;
    } else if (MODE == 1) {
        Aph = g_tpg_hi + (size_t)n * 768 * LDIM;  Apl = g_tpg_lo + (size_t)n * 768 * LDIM;
        Bph = g_tpg_hi + ((size_t)n * 768 + 256) * LDIM;
        Bpl = g_tpg_lo + ((size_t)n * 768 + 256) * LDIM;
    } else {
        Aph = g_tpg_hi + ((size_t)n * 768 + 512 + m0) * LDIM;
        Apl = g_tpg_lo + ((size_t)n * 768 + 512 + m0) * LDIM;
        AKW = 1024;
        Bf = cbuf + (size_t)n * LDIM * LDIM;
        eM = g_M[n]; iZ = g_invZ[n];
    }

    float acc[4][4][4];
#pragma unroll
    for (int a = 0; a < 4; a++)
#pragma unroll
        for (int b = 0; b < 4; b++)
#pragma unroll
            for (int c = 0; c < 4; c++) acc[a][b][c] = 0.f;

    float4 vB[4];   // mode2 B register staging (32x128 fp32 / 256 thr)

    auto cp_stage = [&](int s) {
        const int k0 = s * 32;
        uint16_t* st = smbuf + (size_t)(s % 3) * STAGE;
        uint16_t* Ah = st;            uint16_t* Al = st + APL;
        uint16_t* Bh = st + 2 * APL;  uint16_t* Bl = st + 2 * APL + BPL;
        if (MODE == 1) {
#pragma unroll
            for (int u = 0; u < 2; u++) {
                int idx = tid + 256 * u;                   // 512 chunks
                int row = idx >> 4, seg = (idx & 15) * 8;
                size_t so = (size_t)(k0 + row) * LDIM + m0 + seg;
                cp16(smem_u32(Ah + row * 136 + seg), Aph + so);
                cp16(smem_u32(Al + row * 136 + seg), Apl + so);
            }
        } else {
#pragma unroll
            for (int u = 0; u < 2; u++) {
                int idx = tid + 256 * u;
                int m = idx >> 2, kseg = (idx & 3) * 8;
                size_t so = (size_t)m * AKW + k0 + kseg;
                cp16(smem_u32(Ah + m * 40 + kseg), Aph + so);
                cp16(smem_u32(Al + m * 40 + kseg), Apl + so);
            }
        }
        if (MODE != 2) {
#pragma unroll
            for (int u = 0; u < 2; u++) {
                int idx = tid + 256 * u;
                int row = idx >> 4, seg = (idx & 15) * 8;
                size_t so = (size_t)(k0 + row) * LDIM + j0 + seg;
                cp16(smem_u32(Bh + row * 136 + seg), Bph + so);
                cp16(smem_u32(Bl + row * 136 + seg), Bpl + so);
            }
        }
    };
    auto ldgB = [&](int s) {
        if (MODE == 2 && s < S) {
            const int k0 = s * 32;
#pragma unroll
            for (int u = 0; u < 4; u++) {
                int vi = tid + 256 * u, k = vi >> 5, j4 = (vi & 31) * 4;
                vB[u] = *(const float4*)(Bf + (size_t)(k0 + k) * LDIM + j0 + j4);
            }
        }
    };
    auto stsB = [&](int s) {
        if (MODE == 2) {
            uint16_t* st = smbuf + (size_t)(s % 3) * STAGE;
            uint16_t* Bh = st + 2 * APL;  uint16_t* Bl = st + 2 * APL + BPL;
#pragma unroll
            for (int u = 0; u < 4; u++) {
                int vi = tid + 256 * u, k = vi >> 5, j4 = (vi & 31) * 4;
                float e0 = __expf(vB[u].x - eM), e1 = __expf(vB[u].y - eM);
                float e2 = __expf(vB[u].z - eM), e3 = __expf(vB[u].w - eM);
                wrpair(Bh + k * 136 + j4,     Bl + k * 136 + j4,     e0, e1);
                wrpair(Bh + k * 136 + j4 + 2, Bl + k * 136 + j4 + 2, e2, e3);
            }
        }
    };

    // lane-constant ldmatrix offsets
    const int amr = lane & 15, akc = (lane >> 4) * 8;                 // A non-trans
    const int tkr = (lane & 7) + ((lane >> 4) << 3);                  // A trans k-row
    const int tmc = ((lane >> 3) & 1) * 8;                            // A trans m-col
    const int bkr = lane & 15, bnc = (lane >> 4) * 8;                 // B

    auto compute = [&](int buf) {
        uint16_t* st = smbuf + (size_t)buf * STAGE;
        uint32_t abh = smem_u32(st),            abl = smem_u32(st + APL);
        uint32_t bbh = smem_u32(st + 2 * APL),  bbl = smem_u32(st + 2 * APL + BPL);
#pragma unroll
        for (int ks = 0; ks < 32; ks += 16) {
            uint32_t ah[4][4], al[4][4], bh[4][2], bl[4][2];
#pragma unroll
            for (int mf = 0; mf < 4; mf++) {
                if (MODE == 1) {
                    uint32_t off = (uint32_t)((ks + tkr) * 136 + wm + mf * 16 + tmc) * 2;
                    ldsm4t(ah[mf], abh + off);
                    ldsm4t(al[mf], abl + off);
                } else {
                    uint32_t off = (uint32_t)((wm + mf * 16 + amr) * 40 + ks + akc) * 2;
                    ldsm4(ah[mf], abh + off);
                    ldsm4(al[mf], abl + off);
                }
            }
#pragma unroll
            for (int nq = 0; nq < 2; nq++) {
                uint32_t off = (uint32_t)((ks + bkr) * 136 + wn + nq * 16 + bnc) * 2;
                uint32_t r[4];
                ldsm4t(r, bbh + off);
                bh[nq * 2][0] = r[0]; bh[nq * 2][1] = r[1];
                bh[nq * 2 + 1][0] = r[2]; bh[nq * 2 + 1][1] = r[3];
                ldsm4t(r, bbl + off);
                bl[nq * 2][0] = r[0]; bl[nq * 2][1] = r[1];
                bl[nq * 2 + 1][0] = r[2]; bl[nq * 2 + 1][1] = r[3];
            }
#pragma unroll
            for (int mf = 0; mf < 4; mf++)
#pragma unroll
                for (int nf = 0; nf < 4; nf++) {
                    hmma(acc[mf][nf], ah[mf], bh[nf]);
                    hmma(acc[mf][nf], ah[mf], bl[nf]);
                    hmma(acc[mf][nf], al[mf], bh[nf]);
                }
        }
    };

    // ---- pipeline: 3-stage ring, cp AFTER barrier (wrap-safe), one sync/stage ----
    cp_stage(0); CP_COMMIT();
    cp_stage(1); CP_COMMIT();
    ldgB(0);
    for (int s = 0; s < S; s++) {
        stsB(s);
        ldgB(s + 1);
        if (s + 1 < S) CP_WAIT(1); else CP_WAIT(0);
        __syncthreads();
        if (s + 2 < S) { cp_stage(s + 2); CP_COMMIT(); }
        compute(s % 3);
    }

    // ---- epilogue ----
    const int g8 = lane >> 2, tg = lane & 3;
    float pm = -1e30f, ps = 0.f;   // mode1 fused softmax partial
#pragma unroll
    for (int mf = 0; mf < 4; mf++)
#pragma unroll
        for (int nf = 0; nf < 4; nf++) {
            int r0 = wm + mf * 16 + g8, cc = wn + nf * 8 + tg * 2;
#pragma unroll
            for (int h = 0; h < 2; h++) {
                int row = r0 + h * 8;
                float f0 = acc[mf][nf][h * 2], f1 = acc[mf][nf][h * 2 + 1];
                if (MODE == 0) {
                    size_t o = ((size_t)n * 768 + m0 + row) * LDIM + j0 + cc;
                    wrpair(g_tpg_hi + o, g_tpg_lo + o, f0, f1);
                } else if (MODE == 1) {
                    *(float2*)(cbuf + ((size_t)n * LDIM + m0 + row) * LDIM + j0 + cc) =
                        make_float2(f0, f1);
                    float vm = fmaxf(f0, f1);
                    if (vm > pm) { ps *= __expf(pm - vm); pm = vm; }
                    ps += __expf(f0 - pm) + __expf(f1 - pm);
                } else {
                    const float2 xv = *(const float2*)(x + ((size_t)n * CDIM + m0 + row) * LDIM + j0 + cc);
                    *(float2*)(ybuf + ((size_t)n * CDIM + m0 + row) * LDIM + j0 + cc) =
                        make_float2(f0 * iZ + xv.x, f1 * iZ + xv.y);
                }
            }
        }

    if (MODE == 1) {
        __syncthreads();
        float* rm = (float*)smbuf;
        float* rs = rm + 256;
        rm[tid] = pm; rs[tid] = ps;
        __syncthreads();
        for (int str = 128; str > 0; str >>= 1) {
            if (tid < str) {
                float m2 = rm[tid + str], s2 = rs[tid + str];
                float M = fmaxf(rm[tid], m2);
                rs[tid] = rs[tid] * __expf(rm[tid] - M) + s2 * __expf(m2 - M);
                rm[tid] = M;
            }
            __syncthreads();
        }
        if (tid == 0) {
            int blk = blockIdx.y * 8 + blockIdx.x;
            g_partm[n * 64 + blk] = rm[0];
            g_parts[n * 64 + blk] = rs[0];
        }
    }
}

// ---------------- softmax final combine ----------------
__global__ __launch_bounds__(64) void k_sm_final() {
    __shared__ float rm[64], rs[64];
    const int n = blockIdx.x, tid = threadIdx.x;
    float m = g_partm[n * 64 + tid];
    rm[tid] = m;
    __syncthreads();
    for (int s = 32; s > 0; s >>= 1) {
        if (tid < s) rm[tid] = fmaxf(rm[tid], rm[tid + s]);
        __syncthreads();
    }
    const float M = rm[0];
    __syncthreads();
    rs[tid] = g_parts[n * 64 + tid] * __expf(m - M);
    __syncthreads();
    for (int s = 32; s > 0; s >>= 1) {
        if (tid < s) rs[tid] += rs[tid + s];
        __syncthreads();
    }
    if (tid == 0) { g_M[n] = M; g_invZ[n] = 1.f / rs[0]; }
}

// =====================================================================
extern "C" void kernel_launch(void* const* d_in, const int* in_sizes, int n_in,
                              void* d_out, int out_size) {
    const float* x  = (const float*)d_in[0];
    const float* wt = (const float*)d_in[1];
    const float* wp = (const float*)d_in[2];
    const float* wg = (const float*)d_in[3];
    const float* wr = (const float*)d_in[4];
    float* out = (float*)d_out;
    float* c_out = out;                              // [16,1024,1024]
    float* y_out = out + (size_t)NB * LDIM * LDIM;   // [16,256,32,32]

    constexpr int SM_A = 3 * (2 * 128 * 40 + 2 * 32 * 136) * 2;   // 113664 B
    constexpr int SM_T = 3 * (2 * 32 * 136 + 2 * 32 * 136) * 2;   // 104448 B
    cudaFuncSetAttribute(gemm_mma<0>, cudaFuncAttributeMaxDynamicSharedMemorySize, SM_A);
    cudaFuncSetAttribute(gemm_mma<1>, cudaFuncAttributeMaxDynamicSharedMemorySize, SM_T);
    cudaFuncSetAttribute(gemm_mma<2>, cudaFuncAttributeMaxDynamicSharedMemorySize, SM_A);

    k_w2<<<256, 256>>>(wr, wg);                      // W2 = wr @ wg (fp32)
    k_cvt_w<<<192, 256>>>(wt, wp);                   // planes: wt, wp, W2
    k_cvt_x<<<4096, 256>>>(x);
    gemm_mma<0><<<dim3(8, 6, NB), 256, SM_A>>>(x, c_out, y_out);   // t, p, G2
    gemm_mma<1><<<dim3(8, 8, NB), 256, SM_T>>>(x, c_out, y_out);   // c + partials
    k_sm_final<<<NB, 64>>>();
    gemm_mma<2><<<dim3(8, 2, NB), 256, SM_A>>>(x, c_out, y_out);   // y direct
}

// round 17
// speedup vs baseline: 1.9199x; 1.9199x over previous
#include <cuda_runtime.h>
#include <cuda_bf16.h>
#include <cuda_fp16.h>
#include <stdint.h>
#include <math.h>

#define LDIM 1024
#define CDIM 256
#define NB   16

// ---------------- scratch (device globals) ----------------
__device__ uint16_t g_w_f16[768 * 256];                      // wt, wp, W2 (fp16 single)
__device__ float    g_w2f[256 * 256];                        // W2 = wr @ wg (fp32)
__device__ uint16_t g_x_hi[16ull * 256 * 1024], g_x_lo[16ull * 256 * 1024];   // fp16 hi/lo
__device__ uint16_t g_tp_hi[2ull * 16 * 256 * 1024], g_tp_lo[2ull * 16 * 256 * 1024]; // t,p bf16 hi/lo
__device__ uint16_t g_g2h[16ull * 256 * 1024];               // G2 = W2@x (fp16 single)
__device__ float g_partm[16 * 64], g_parts[16 * 64], g_M[16], g_invZ[16];

// ---------------- helpers ----------------
__device__ __forceinline__ uint32_t smem_u32(const void* p) {
    uint32_t a;
    asm("{ .reg .u64 t; cvta.to.shared.u64 t, %1; cvt.u32.u64 %0, t; }" : "=r"(a) : "l"(p));
    return a;
}
__device__ __forceinline__ void hmma_bf(float* c, const uint32_t* a, const uint32_t* b) {
    asm volatile(
        "mma.sync.aligned.m16n8k16.row.col.f32.bf16.bf16.f32 "
        "{%0,%1,%2,%3}, {%4,%5,%6,%7}, {%8,%9}, {%0,%1,%2,%3};"
        : "+f"(c[0]), "+f"(c[1]), "+f"(c[2]), "+f"(c[3])
        : "r"(a[0]), "r"(a[1]), "r"(a[2]), "r"(a[3]), "r"(b[0]), "r"(b[1]));
}
__device__ __forceinline__ void hmma_h(float* c, const uint32_t* a, const uint32_t* b) {
    asm volatile(
        "mma.sync.aligned.m16n8k16.row.col.f32.f16.f16.f32 "
        "{%0,%1,%2,%3}, {%4,%5,%6,%7}, {%8,%9}, {%0,%1,%2,%3};"
        : "+f"(c[0]), "+f"(c[1]), "+f"(c[2]), "+f"(c[3])
        : "r"(a[0]), "r"(a[1]), "r"(a[2]), "r"(a[3]), "r"(b[0]), "r"(b[1]));
}
__device__ __forceinline__ void ldsm4(uint32_t* r, uint32_t addr) {
    asm volatile("ldmatrix.sync.aligned.m8n8.x4.shared.b16 {%0,%1,%2,%3}, [%4];"
                 : "=r"(r[0]), "=r"(r[1]), "=r"(r[2]), "=r"(r[3]) : "r"(addr));
}
__device__ __forceinline__ void ldsm4t(uint32_t* r, uint32_t addr) {
    asm volatile("ldmatrix.sync.aligned.m8n8.x4.trans.shared.b16 {%0,%1,%2,%3}, [%4];"
                 : "=r"(r[0]), "=r"(r[1]), "=r"(r[2]), "=r"(r[3]) : "r"(addr));
}
__device__ __forceinline__ void cp16(uint32_t daddr, const void* src) {
    asm volatile("cp.async.cg.shared.global [%0], [%1], 16;" ::"r"(daddr), "l"(src) : "memory");
}
#define CP_COMMIT() asm volatile("cp.async.commit_group;" ::: "memory")
#define CP_WAIT(n)  asm volatile("cp.async.wait_group %0;" ::"n"(n) : "memory")

__device__ __forceinline__ uint32_t pk2(float a, float b) {       // bf16x2
    __nv_bfloat162 t = __floats2bfloat162_rn(a, b);
    return reinterpret_cast<uint32_t&>(t);
}
__device__ __forceinline__ uint32_t pkh2(float a, float b) {      // fp16x2
    __half2 t = __floats2half2_rn(a, b);
    return reinterpret_cast<uint32_t&>(t);
}
__device__ __forceinline__ void wrpair(uint16_t* hi, uint16_t* lo, float a, float b) { // bf16 split
    float ha = __bfloat162float(__float2bfloat16(a));
    float hb = __bfloat162float(__float2bfloat16(b));
    *(uint32_t*)hi = pk2(a, b);
    *(uint32_t*)lo = pk2(a - ha, b - hb);
}
__device__ __forceinline__ void wrpair_h(uint16_t* hi, uint16_t* lo, float a, float b) { // fp16 split
    float ha = __half2float(__float2half_rn(a));
    float hb = __half2float(__float2half_rn(b));
    *(uint32_t*)hi = pkh2(a, b);
    *(uint32_t*)lo = pkh2(a - ha, b - hb);
}

// ---------------- W2 = wr @ wg (fp32, tiny) ----------------
__global__ __launch_bounds__(256) void k_w2(const float* __restrict__ wr,
                                            const float* __restrict__ wg) {
    __shared__ float wrow[256];
    const int c = blockIdx.x, i = threadIdx.x;
    wrow[i] = wr[c * 256 + i];
    __syncthreads();
    float s = 0.f;
#pragma unroll 8
    for (int a = 0; a < 256; a++) s = fmaf(wrow[a], wg[a * 256 + i], s);
    g_w2f[c * 256 + i] = s;
}

// ---------------- conversion passes ----------------
__global__ __launch_bounds__(256) void k_cvt_w(const float* __restrict__ wt,
                                               const float* __restrict__ wp) {
    int idx = blockIdx.x * 256 + threadIdx.x;
    int e = idx * 4, row = e >> 8, col = e & 255;
    const float* s = (row < 256) ? wt + (size_t)row * 256
                   : (row < 512) ? wp + (size_t)(row - 256) * 256
                                 : g_w2f + (size_t)(row - 512) * 256;
    float4 v = *(const float4*)(s + col);
    size_t o = (size_t)row * 256 + col;
    *(uint2*)(g_w_f16 + o) = make_uint2(pkh2(v.x, v.y), pkh2(v.z, v.w));
}
__global__ __launch_bounds__(256) void k_cvt_x(const float* __restrict__ x) {
    size_t idx = (size_t)blockIdx.x * 256 + threadIdx.x;
    float4 v = ((const float4*)x)[idx];
    size_t o = idx * 4;
    wrpair_h(g_x_hi + o, g_x_lo + o, v.x, v.y);
    wrpair_h(g_x_hi + o + 2, g_x_lo + o + 2, v.z, v.w);
}

// =====================================================================
// Pipelined mma.sync GEMM: 128x128 block, BK=16, 4-stage ring, one sync
// per stage, 2 CTAs/SM (the proven R15 pipeline).
// MODE 0: t,p (bf16 hi/lo out) + G2 (fp16 out); A = W fp16 single, B = x fp16 split, 2-MMA
// MODE 1: c = t^T p; bf16 3-term (strict output) + fused softmax partial
// MODE 2: y = x + iZ*(G2 @ exp(c-M)); A = G2 fp16 single, B = exp fp16 split, 2-MMA
// =====================================================================
template <int MODE>
__global__ __launch_bounds__(256, 2) void gemm_mma(const float* __restrict__ x,
                                                   float* __restrict__ cbuf,
                                                   float* __restrict__ ybuf) {
    constexpr int S     = (MODE == 2) ? 64 : 16;               // K/16 stages
    constexpr int APL   = (MODE == 1) ? 16 * 136 : 128 * 24;   // A plane elems
    constexpr int NAP   = (MODE == 1) ? 2 : 1;                 // A planes
    constexpr int BPL   = 16 * 136;
    constexpr int STAGE = NAP * APL + 2 * BPL;
    extern __shared__ __align__(16) uint16_t smbuf[];

    const int tid = threadIdx.x, lane = tid & 31, wid = tid >> 5;
    const int n = blockIdx.z, j0 = blockIdx.x * 128, m0 = blockIdx.y * 128;
    const int wm = (wid & 1) * 64, wn = (wid >> 1) * 32;

    const uint16_t *Aph, *Apl = nullptr, *Bph = nullptr, *Bpl = nullptr;
    const float* Bf = nullptr;
    float eM = 0.f, iZ = 1.f;
    size_t AKW = 256;
    if (MODE == 0) {
        Aph = g_w_f16 + (size_t)m0 * 256;
        Bph = g_x_hi + (size_t)n * CDIM * LDIM;  Bpl = g_x_lo + (size_t)n * CDIM * LDIM;
    } else if (MODE == 1) {
        Aph = g_tp_hi + (size_t)n * 512 * LDIM;  Apl = g_tp_lo + (size_t)n * 512 * LDIM;
        Bph = g_tp_hi + ((size_t)n * 512 + 256) * LDIM;
        Bpl = g_tp_lo + ((size_t)n * 512 + 256) * LDIM;
    } else {
        Aph = g_g2h + ((size_t)n * 256 + m0) * LDIM;
        AKW = 1024;
        Bf = cbuf + (size_t)n * LDIM * LDIM;
        eM = g_M[n]; iZ = g_invZ[n];
    }

    float acc[4][4][4];
#pragma unroll
    for (int a = 0; a < 4; a++)
#pragma unroll
        for (int b = 0; b < 4; b++)
#pragma unroll
            for (int c = 0; c < 4; c++) acc[a][b][c] = 0.f;

    float4 vB[2];   // mode2 B register staging (16x128 fp32 / 256 thr)

    auto cp_stage = [&](int s) {
        const int k0 = s * 16;
        uint16_t* st = smbuf + (size_t)(s & 3) * STAGE;
        uint16_t* Ah = st;
        uint16_t* Al = st + APL;                       // mode1 only
        uint16_t* Bh = st + NAP * APL;
        uint16_t* Bl = st + NAP * APL + BPL;
        if (MODE == 1) {
            int row = tid >> 4, seg = (tid & 15) * 8;
            size_t so = (size_t)(k0 + row) * LDIM + m0 + seg;
            cp16(smem_u32(Ah + row * 136 + seg), Aph + so);
            cp16(smem_u32(Al + row * 136 + seg), Apl + so);
        } else {
            int m = tid >> 1, kseg = (tid & 1) * 8;
            size_t so = (size_t)m * AKW + k0 + kseg;
            cp16(smem_u32(Ah + m * 24 + kseg), Aph + so);
        }
        if (MODE != 2) {
            int row = tid >> 4, seg = (tid & 15) * 8;
            size_t so = (size_t)(k0 + row) * LDIM + j0 + seg;
            cp16(smem_u32(Bh + row * 136 + seg), Bph + so);
            cp16(smem_u32(Bl + row * 136 + seg), Bpl + so);
        }
    };
    auto ldgB = [&](int s) {
        if (MODE == 2 && s < S) {
            const int k0 = s * 16;
#pragma unroll
            for (int u = 0; u < 2; u++) {
                int vi = tid + 256 * u, k = vi >> 5, j4 = (vi & 31) * 4;
                vB[u] = *(const float4*)(Bf + (size_t)(k0 + k) * LDIM + j0 + j4);
            }
        }
    };
    auto stsB = [&](int s) {
        if (MODE == 2) {
            uint16_t* st = smbuf + (size_t)(s & 3) * STAGE;
            uint16_t* Bh = st + NAP * APL;  uint16_t* Bl = st + NAP * APL + BPL;
#pragma unroll
            for (int u = 0; u < 2; u++) {
                int vi = tid + 256 * u, k = vi >> 5, j4 = (vi & 31) * 4;
                float e0 = __expf(vB[u].x - eM), e1 = __expf(vB[u].y - eM);
                float e2 = __expf(vB[u].z - eM), e3 = __expf(vB[u].w - eM);
                wrpair_h(Bh + k * 136 + j4,     Bl + k * 136 + j4,     e0, e1);
                wrpair_h(Bh + k * 136 + j4 + 2, Bl + k * 136 + j4 + 2, e2, e3);
            }
        }
    };

    // lane-constant ldmatrix offsets
    const int amr = lane & 15, akc = (lane >> 4) * 8;                 // A non-trans
    const int tkr = (lane & 7) + ((lane >> 4) << 3);                  // A trans k-row
    const int tmc = ((lane >> 3) & 1) * 8;                            // A trans m-col
    const int bkr = lane & 15, bnc = (lane >> 4) * 8;                 // B

    auto compute = [&](int buf) {
        uint16_t* st = smbuf + (size_t)buf * STAGE;
        uint32_t abh = smem_u32(st), abl = smem_u32(st + APL);
        uint32_t bbh = smem_u32(st + NAP * APL), bbl = smem_u32(st + NAP * APL + BPL);
        uint32_t ah[4][4], bh[4][2], bl[4][2];
#pragma unroll
        for (int nq = 0; nq < 2; nq++) {
            uint32_t off = (uint32_t)(bkr * 136 + wn + nq * 16 + bnc) * 2;
            uint32_t r[4];
            ldsm4t(r, bbh + off);
            bh[nq * 2][0] = r[0]; bh[nq * 2][1] = r[1];
            bh[nq * 2 + 1][0] = r[2]; bh[nq * 2 + 1][1] = r[3];
            ldsm4t(r, bbl + off);
            bl[nq * 2][0] = r[0]; bl[nq * 2][1] = r[1];
            bl[nq * 2 + 1][0] = r[2]; bl[nq * 2 + 1][1] = r[3];
        }
        if (MODE == 1) {
            uint32_t al[4][4];
#pragma unroll
            for (int mf = 0; mf < 4; mf++) {
                uint32_t off = (uint32_t)(tkr * 136 + wm + mf * 16 + tmc) * 2;
                ldsm4t(ah[mf], abh + off);
                ldsm4t(al[mf], abl + off);
            }
#pragma unroll
            for (int mf = 0; mf < 4; mf++)
#pragma unroll
                for (int nf = 0; nf < 4; nf++) {
                    hmma_bf(acc[mf][nf], ah[mf], bh[nf]);
                    hmma_bf(acc[mf][nf], ah[mf], bl[nf]);
                    hmma_bf(acc[mf][nf], al[mf], bh[nf]);
                }
        } else {
#pragma unroll
            for (int mf = 0; mf < 4; mf++) {
                uint32_t off = (uint32_t)((wm + mf * 16 + amr) * 24 + akc) * 2;
                ldsm4(ah[mf], abh + off);
            }
#pragma unroll
            for (int mf = 0; mf < 4; mf++)
#pragma unroll
                for (int nf = 0; nf < 4; nf++) {
                    hmma_h(acc[mf][nf], ah[mf], bh[nf]);
                    hmma_h(acc[mf][nf], ah[mf], bl[nf]);
                }
        }
    };

    // ---- pipeline: 4-stage ring, prefetch distance 2, one sync/stage (R15) ----
    cp_stage(0); CP_COMMIT();
    cp_stage(1); CP_COMMIT();
    ldgB(0);
    for (int s = 0; s < S; s++) {
        stsB(s);
        ldgB(s + 1);
        if (s + 2 < S) { cp_stage(s + 2); CP_COMMIT(); CP_WAIT(2); }
        else if (s + 1 < S) { CP_WAIT(1); }
        else { CP_WAIT(0); }
        __syncthreads();
        compute(s & 3);
    }

    // ---- epilogue ----
    const int g8 = lane >> 2, tg = lane & 3;
    float pm = -1e30f, ps = 0.f;   // mode1 fused softmax partial
#pragma unroll
    for (int mf = 0; mf < 4; mf++)
#pragma unroll
        for (int nf = 0; nf < 4; nf++) {
            int r0 = wm + mf * 16 + g8, cc = wn + nf * 8 + tg * 2;
#pragma unroll
            for (int h = 0; h < 2; h++) {
                int row = r0 + h * 8;
                float f0 = acc[mf][nf][h * 2], f1 = acc[mf][nf][h * 2 + 1];
                if (MODE == 0) {
                    if (m0 < 512) {
                        size_t o = ((size_t)n * 512 + m0 + row) * LDIM + j0 + cc;
                        wrpair(g_tp_hi + o, g_tp_lo + o, f0, f1);
                    } else {
                        size_t o = ((size_t)n * 256 + m0 - 512 + row) * LDIM + j0 + cc;
                        *(uint32_t*)(g_g2h + o) = pkh2(f0, f1);
                    }
                } else if (MODE == 1) {
                    *(float2*)(cbuf + ((size_t)n * LDIM + m0 + row) * LDIM + j0 + cc) =
                        make_float2(f0, f1);
                    float vm = fmaxf(f0, f1);
                    if (vm > pm) { ps *= __expf(pm - vm); pm = vm; }
                    ps += __expf(f0 - pm) + __expf(f1 - pm);
                } else {
                    const float2 xv = *(const float2*)(x + ((size_t)n * CDIM + m0 + row) * LDIM + j0 + cc);
                    *(float2*)(ybuf + ((size_t)n * CDIM + m0 + row) * LDIM + j0 + cc) =
                        make_float2(f0 * iZ + xv.x, f1 * iZ + xv.y);
                }
            }
        }

    if (MODE == 1) {
        __syncthreads();
        float* rm = (float*)smbuf;
        float* rs = rm + 256;
        rm[tid] = pm; rs[tid] = ps;
        __syncthreads();
        for (int str = 128; str > 0; str >>= 1) {
            if (tid < str) {
                float m2 = rm[tid + str], s2 = rs[tid + str];
                float M = fmaxf(rm[tid], m2);
                rs[tid] = rs[tid] * __expf(rm[tid] - M) + s2 * __expf(m2 - M);
                rm[tid] = M;
            }
            __syncthreads();
        }
        if (tid == 0) {
            int blk = blockIdx.y * 8 + blockIdx.x;
            g_partm[n * 64 + blk] = rm[0];
            g_parts[n * 64 + blk] = rs[0];
        }
    }
}

// ---------------- softmax final combine ----------------
__global__ __launch_bounds__(64) void k_sm_final() {
    __shared__ float rm[64], rs[64];
    const int n = blockIdx.x, tid = threadIdx.x;
    float m = g_partm[n * 64 + tid];
    rm[tid] = m;
    __syncthreads();
    for (int s = 32; s > 0; s >>= 1) {
        if (tid < s) rm[tid] = fmaxf(rm[tid], rm[tid + s]);
        __syncthreads();
    }
    const float M = rm[0];
    __syncthreads();
    rs[tid] = g_parts[n * 64 + tid] * __expf(m - M);
    __syncthreads();
    for (int s = 32; s > 0; s >>= 1) {
        if (tid < s) rs[tid] += rs[tid + s];
        __syncthreads();
    }
    if (tid == 0) { g_M[n] = M; g_invZ[n] = 1.f / rs[0]; }
}

// =====================================================================
extern "C" void kernel_launch(void* const* d_in, const int* in_sizes, int n_in,
                              void* d_out, int out_size) {
    const float* x  = (const float*)d_in[0];
    const float* wt = (const float*)d_in[1];
    const float* wp = (const float*)d_in[2];
    const float* wg = (const float*)d_in[3];
    const float* wr = (const float*)d_in[4];
    float* out = (float*)d_out;
    float* c_out = out;                              // [16,1024,1024]
    float* y_out = out + (size_t)NB * LDIM * LDIM;   // [16,256,32,32]

    constexpr int SM_A = 4 * (128 * 24 + 2 * 16 * 136) * 2;       // 59392 B (modes 0,2)
    constexpr int SM_T = 4 * (2 * 16 * 136 + 2 * 16 * 136) * 2;   // 69632 B (mode 1)
    cudaFuncSetAttribute(gemm_mma<0>, cudaFuncAttributeMaxDynamicSharedMemorySize, SM_A);
    cudaFuncSetAttribute(gemm_mma<1>, cudaFuncAttributeMaxDynamicSharedMemorySize, SM_T);
    cudaFuncSetAttribute(gemm_mma<2>, cudaFuncAttributeMaxDynamicSharedMemorySize, SM_A);

    k_w2<<<256, 256>>>(wr, wg);                      // W2 = wr @ wg (fp32)
    k_cvt_w<<<192, 256>>>(wt, wp);                   // fp16 plane: wt, wp, W2
    k_cvt_x<<<4096, 256>>>(x);                       // fp16 hi/lo planes of x
    gemm_mma<0><<<dim3(8, 6, NB), 256, SM_A>>>(x, c_out, y_out);   // t, p, G2
    gemm_mma<1><<<dim3(8, 8, NB), 256, SM_T>>>(x, c_out, y_out);   // c + partials
    k_sm_final<<<NB, 64>>>();
    gemm_mma<2><<<dim3(8, 2, NB), 256, SM_A>>>(x, c_out, y_out);   // y direct
}